// round 16
// baseline (speedup 1.0000x reference)
#include <cuda_runtime.h>
#include <mma.h>
#include <cuda_fp16.h>
#include <math.h>
#include <stdint.h>

using namespace nvcuda;

// ---------------- problem constants ----------------
#define NND     25000
#define INDIM   128
#define HID     256
#define NHEADS  4
#define HEADDIM 64
#define NLAYERS 3
#define NE      500000
#define ETOT    (NE + NND)   // reference appends self-loops

// packed weight-split layout (element offsets)
#define WOFF_ENC  0
#define WOFF_WL   32768
#define WOFF_WR   229376
#define WOFF_SK   425984
#define WOFF_OUT  622592
#define WTOT      688128

// ---------------- device scratch (static, no allocation) ----------------
__device__ float  g_xl  [NND * HID];
__device__ float  g_xr  [NND * HID];
__device__ float  g_skip[NND * HID];
__device__ float  g_agg [NND * HID];   // gat edge aggregation (pre-skip/LN)
__device__ float  g_part[NND * 4];     // head partial dots
__device__ __half g_hh  [NND * HID];   // h hi-halves
__device__ __half g_hl  [NND * HID];   // h lo-halves
__device__ __half g_exh [NND * INDIM]; // x hi
__device__ __half g_exl [NND * INDIM]; // x lo
__device__ __half g_wh  [WTOT];        // weights hi
__device__ __half g_wl  [WTOT];        // weights lo
__device__ int    g_deg [NND];
__device__ int    g_off [NND + 1];
__device__ int    g_cur [NND];
__device__ int    g_csr [ETOT];
__device__ int    g_incl[NND];
__device__ int    g_bsum[64];
__device__ int    g_is64;

// float scratch ids: 1=xl 2=xr 3=skip
__device__ __forceinline__ float* fbuf_ptr(int id) {
    switch (id) {
        case 1: return g_xl;
        case 2: return g_xr;
        default: return g_skip;
    }
}

__device__ __forceinline__ int load_idx(const void* ei, long long pos) {
    if (g_is64) return (int)((const long long*)ei)[pos];
    return ((const int*)ei)[pos];
}

// ---------------- hi/lo split helpers ----------------
__global__ void split_all_kernel(const float* __restrict__ encW,
                                 const float* __restrict__ Wl,
                                 const float* __restrict__ Wr,
                                 const float* __restrict__ skW,
                                 const float* __restrict__ outW) {
    int i = blockIdx.x * blockDim.x + threadIdx.x;
    if (i >= WTOT) return;
    const float* src; int local;
    if (i < WOFF_WL)       { src = encW; local = i - WOFF_ENC; }
    else if (i < WOFF_SK)  { src = (i < WOFF_WR) ? Wl : Wr;
                             local = i - ((i < WOFF_WR) ? WOFF_WL : WOFF_WR); }
    else if (i < WOFF_OUT) { src = skW;  local = i - WOFF_SK; }
    else                   { src = outW; local = i - WOFF_OUT; }
    float v = src[local];
    __half hi = __float2half_rn(v);
    g_wh[i] = hi;
    g_wl[i] = __float2half_rn(v - __half2float(hi));
}

__global__ void split_x_kernel(const float* __restrict__ src) {
    int i = blockIdx.x * blockDim.x + threadIdx.x;
    if (i < NND * INDIM) {
        float v = src[i];
        __half hi = __float2half_rn(v);
        g_exh[i] = hi;
        g_exl[i] = __float2half_rn(v - __half2float(hi));
    }
}

// ---------------- CSR construction ----------------
// zero degrees + dtype-detect (edge_index declared int64, but JAX x64-disabled
// silently yields int32; true int64 <2^31 has all odd 32-bit words zero)
__global__ void zerodetect_kernel(const void* ei) {
    int i = blockIdx.x * blockDim.x + threadIdx.x;
    if (i < NND) g_deg[i] = 0;
    if (blockIdx.x == 0 && threadIdx.x == 0) {
        const int* w = (const int*)ei;
        int nz = 0;
        #pragma unroll
        for (int k = 0; k < 64; k++) nz |= w[2 * k + 1];
        g_is64 = (nz == 0) ? 1 : 0;
    }
}

__global__ void count_kernel(const void* __restrict__ ei) {
    int e = blockIdx.x * blockDim.x + threadIdx.x;
    if (e >= ETOT) return;
    int dst = (e < NE) ? load_idx(ei, (long long)NE + e) : (e - NE);
    atomicAdd(&g_deg[dst], 1);
}

__global__ void scan1_kernel() {
    __shared__ int sh[512];
    int idx = blockIdx.x * 512 + threadIdx.x;
    int v = (idx < NND) ? g_deg[idx] : 0;
    sh[threadIdx.x] = v;
    __syncthreads();
    #pragma unroll
    for (int d = 1; d < 512; d <<= 1) {
        int t = (threadIdx.x >= d) ? sh[threadIdx.x - d] : 0;
        __syncthreads();
        sh[threadIdx.x] += t;
        __syncthreads();
    }
    if (idx < NND) g_incl[idx] = sh[threadIdx.x];
    if (threadIdx.x == 511) g_bsum[blockIdx.x] = sh[511];
}

__global__ void scan2_kernel(int nblk) {
    __shared__ int sh[64];
    int t = threadIdx.x;
    int v = (t < nblk) ? g_bsum[t] : 0;
    sh[t] = v;
    __syncthreads();
    #pragma unroll
    for (int d = 1; d < 64; d <<= 1) {
        int u = (t >= d) ? sh[t - d] : 0;
        __syncthreads();
        sh[t] += u;
        __syncthreads();
    }
    if (t < nblk) g_bsum[t] = sh[t] - v;     // exclusive
    if (t == nblk - 1) g_off[NND] = sh[t];   // total
}

__global__ void scan3_kernel() {
    int idx = blockIdx.x * 512 + threadIdx.x;
    if (idx < NND) {
        int e = g_incl[idx] - g_deg[idx] + g_bsum[blockIdx.x];
        g_off[idx] = e;
        g_cur[idx] = e;
    }
}

__global__ void fill_kernel(const void* __restrict__ ei) {
    int e = blockIdx.x * blockDim.x + threadIdx.x;
    if (e >= ETOT) return;
    int src, dst;
    if (e < NE) { src = load_idx(ei, e); dst = load_idx(ei, (long long)NE + e); }
    else        { src = e - NE;          dst = e - NE; }
    int pos = atomicAdd(&g_cur[dst], 1);
    g_csr[pos] = src;
}

// ---------------- cp.async helpers ----------------
__device__ __forceinline__ void cp_async16(unsigned saddr, const void* gptr, bool pred) {
    int sz = pred ? 16 : 0;
    asm volatile("cp.async.cg.shared.global [%0], [%1], 16, %2;\n"
                 :: "r"(saddr), "l"(gptr), "r"(sz));
}
#define CP_COMMIT() asm volatile("cp.async.commit_group;\n" ::: "memory")
#define CP_WAIT0()  asm volatile("cp.async.wait_group 0;\n" ::: "memory")

// ---------------- 3xFP16-split tensor-core GEMM, cp.async double-buffered --
// C[N,256] = A[N,K] @ B[K,256], operands pre-split hi/lo.
// D = Ahi*Bhi + Ahi*Blo + Alo*Bhi, fp32 acc. Block 128x128, 8 warps,
// warp tile 32x64 = 2x4 wmma m16n16k16, BK=16.
// MODE: 0 = fp32 C (+bias,relu when bias nonnull)
//       1 = write h hi/lo halves (encoder)
//       2 = fused head: bias+relu then dot with W2 -> g_part
// blockIdx.y: j = y>>1 selects B/C/bias, bc = y&1 selects 128-col half.

#define A_LDM 24    // halves; 48B row stride
#define B_LDM 136   // halves; 272B row stride
#define ASTAGE_B 12288
#define BSTAGE_B 8704
#define SMEM_TILES (2*ASTAGE_B + 2*BSTAGE_B)   // 41984

template <int NB, int MODE>
__global__ __launch_bounds__(256, 2)
void hgemm_kernel(int aId,                       // 0: g_hh/g_hl (K=256), 1: g_exh/g_exl (K=128)
                  int bOff0, int bOff1, int bOff2,
                  const float* __restrict__ bias0, const float* __restrict__ bias2,
                  const float* __restrict__ w2,
                  int c0, int c1, int c2,
                  int Nrows, int K) {
    const __half* Ah = aId ? g_exh : g_hh;
    const __half* Al = aId ? g_exl : g_hl;

    const int j  = blockIdx.y >> 1;
    const int bc = blockIdx.y & 1;
    const int bOff = (NB == 1 || j == 0) ? bOff0 : ((j == 1) ? bOff1 : bOff2);
    float* C = fbuf_ptr((NB == 1 || j == 0) ? c0 : ((j == 1) ? c1 : c2));
    const float* bias = (NB == 1 || j == 0) ? bias0 : ((j == 2) ? bias2 : nullptr);

    __shared__ __align__(16) unsigned char smem_raw[SMEM_TILES];
    const unsigned sbase = (unsigned)__cvta_generic_to_shared(smem_raw);

    const int tid  = threadIdx.x;
    const int lane = tid & 31;
    const int wid  = tid >> 5;
    const int warp_m = wid & 3;
    const int warp_n = wid >> 2;

    const int br = blockIdx.x;
    const int rowBase = br * 128 + warp_m * 32;
    const int colBase = bc * 128 + warp_n * 64;

    wmma::fragment<wmma::accumulator, 16, 16, 16, float> acc[2][4];
    #pragma unroll
    for (int mt = 0; mt < 2; mt++)
        #pragma unroll
        for (int nt = 0; nt < 4; nt++)
            wmma::fill_fragment(acc[mt][nt], 0.f);

    const int arow = tid >> 1, acol = (tid & 1) * 8;
    const int bk = tid >> 4, bn = (tid & 15) * 8;

    const int rg = br * 128 + arow;
    const bool aOK = (rg < Nrows);
    const int rgs = aOK ? rg : 0;
    const int nIter = K >> 4;

    const unsigned aslot = (unsigned)(arow * A_LDM + acol) * 2u;
    const unsigned bslot = (unsigned)(bk * B_LDM + bn) * 2u;

    auto issueTile = [&](int kt, int s) {
        int k0 = kt << 4;
        size_t aoff = (size_t)rgs * K + k0 + acol;
        cp_async16(sbase + s * ASTAGE_B + aslot, Ah + aoff, aOK);
        cp_async16(sbase + s * ASTAGE_B + ASTAGE_B / 2 + aslot, Al + aoff, aOK);
        size_t boff = (size_t)bOff + (size_t)(k0 + bk) * HID + bc * 128 + bn;
        cp_async16(sbase + 2 * ASTAGE_B + s * BSTAGE_B + bslot, g_wh + boff, true);
        cp_async16(sbase + 2 * ASTAGE_B + s * BSTAGE_B + BSTAGE_B / 2 + bslot, g_wl + boff, true);
    };
    auto AhS = [&](int s) { return (__half*)(smem_raw + s * ASTAGE_B); };
    auto AlS = [&](int s) { return (__half*)(smem_raw + s * ASTAGE_B + ASTAGE_B / 2); };
    auto BhS = [&](int s) { return (__half*)(smem_raw + 2 * ASTAGE_B + s * BSTAGE_B); };
    auto BlS = [&](int s) { return (__half*)(smem_raw + 2 * ASTAGE_B + s * BSTAGE_B + BSTAGE_B / 2); };

    issueTile(0, 0);
    CP_COMMIT();

    for (int kt = 0; kt < nIter; kt++) {
        const int cur = kt & 1, nxt = cur ^ 1;
        CP_WAIT0();
        __syncthreads();
        if (kt + 1 < nIter) {
            issueTile(kt + 1, nxt);
            CP_COMMIT();
        }

        wmma::fragment<wmma::matrix_a, 16, 16, 16, __half, wmma::row_major> a_hi[2], a_lo[2];
        #pragma unroll
        for (int mt = 0; mt < 2; mt++) {
            int mr = warp_m * 32 + mt * 16;
            wmma::load_matrix_sync(a_hi[mt], AhS(cur) + mr * A_LDM, A_LDM);
            wmma::load_matrix_sync(a_lo[mt], AlS(cur) + mr * A_LDM, A_LDM);
        }
        #pragma unroll
        for (int nt = 0; nt < 4; nt++) {
            int nc = warp_n * 64 + nt * 16;
            wmma::fragment<wmma::matrix_b, 16, 16, 16, __half, wmma::row_major> b_hi, b_lo;
            wmma::load_matrix_sync(b_hi, BhS(cur) + nc, B_LDM);
            wmma::load_matrix_sync(b_lo, BlS(cur) + nc, B_LDM);
            #pragma unroll
            for (int mt = 0; mt < 2; mt++) {
                wmma::mma_sync(acc[mt][nt], a_hi[mt], b_hi, acc[mt][nt]);
                wmma::mma_sync(acc[mt][nt], a_hi[mt], b_lo, acc[mt][nt]);
                wmma::mma_sync(acc[mt][nt], a_lo[mt], b_hi, acc[mt][nt]);
            }
        }
    }
    __syncthreads();

    // ---- epilogue: sbuf aliases tile memory
    float* sbuf = (float*)smem_raw + wid * 16 * 20;
    #pragma unroll
    for (int mt = 0; mt < 2; mt++) {
        float pdot = 0.f;
        const int r  = lane >> 1;
        const int cb = (lane & 1) * 8;
        const int grow = rowBase + mt * 16 + r;
        #pragma unroll
        for (int nt = 0; nt < 4; nt++) {
            wmma::store_matrix_sync(sbuf, acc[mt][nt], 20, wmma::mem_row_major);
            __syncwarp();
            int gcol = colBase + nt * 16 + cb;
            if (grow < Nrows) {
                float vv[8];
                #pragma unroll
                for (int i = 0; i < 8; i++) {
                    float t = sbuf[r * 20 + cb + i];
                    if (bias) t = fmaxf(t + bias[gcol + i], 0.f);
                    vv[i] = t;
                }
                if (MODE == 2) {
                    #pragma unroll
                    for (int i = 0; i < 8; i++)
                        pdot = fmaf(vv[i], w2[gcol + i], pdot);
                } else if (MODE == 1) {
                    __half hh[8], hl[8];
                    #pragma unroll
                    for (int i = 0; i < 8; i++) {
                        __half hi = __float2half_rn(vv[i]);
                        hh[i] = hi;
                        hl[i] = __float2half_rn(vv[i] - __half2float(hi));
                    }
                    size_t off = (size_t)grow * HID + gcol;
                    *(uint4*)(g_hh + off) = *(const uint4*)hh;
                    *(uint4*)(g_hl + off) = *(const uint4*)hl;
                } else {
                    float4* cp = (float4*)(C + (size_t)grow * HID + gcol);
                    cp[0] = make_float4(vv[0], vv[1], vv[2], vv[3]);
                    cp[1] = make_float4(vv[4], vv[5], vv[6], vv[7]);
                }
            }
            __syncwarp();
        }
        if (MODE == 2) {
            pdot += __shfl_xor_sync(0xffffffffu, pdot, 1);
            if ((lane & 1) == 0 && grow < Nrows)
                g_part[grow * 4 + bc * 2 + warp_n] = pdot;
        }
    }
}

// ---------------- GATv2 edge aggregation only (agg*inv -> g_agg) ----------
// one warp per node; lane owns channels [lane*8, lane*8+8), head = lane/8
// edge loop unrolled x4 (all gathers issued before any reduction).
__global__ __launch_bounds__(256)
void gat_edge_kernel(const float* __restrict__ att_l) {
    const int warp = threadIdx.x >> 5;
    const int lane = threadIdx.x & 31;
    const int i = blockIdx.x * 8 + warp;
    if (i >= NND) return;

    const int head = lane >> 3;
    const int cbase = lane * 8;

    float xr[8], attv[8];
    {
        const float4* p = (const float4*)(g_xr + (size_t)i * HID + cbase);
        float4 a = p[0], b = p[1];
        xr[0]=a.x; xr[1]=a.y; xr[2]=a.z; xr[3]=a.w;
        xr[4]=b.x; xr[5]=b.y; xr[6]=b.z; xr[7]=b.w;
        #pragma unroll
        for (int k = 0; k < 8; k++)
            attv[k] = att_l[head * HEADDIM + (lane & 7) * 8 + k];
    }

    float m = -INFINITY, s = 0.f;
    float accv[8];
    #pragma unroll
    for (int k = 0; k < 8; k++) accv[k] = 0.f;

    auto process = [&](const float4& a, const float4& b) {
        float xlv[8] = {a.x, a.y, a.z, a.w, b.x, b.y, b.z, b.w};
        float partial = 0.f;
        #pragma unroll
        for (int k = 0; k < 8; k++) {
            float t = xlv[k] + xr[k];
            t = (t > 0.f) ? t : 0.2f * t;          // leaky_relu 0.2
            partial = fmaf(t, attv[k], partial);
        }
        partial += __shfl_down_sync(0xffffffffu, partial, 4);
        partial += __shfl_down_sync(0xffffffffu, partial, 2);
        partial += __shfl_down_sync(0xffffffffu, partial, 1);
        const float logit = __shfl_sync(0xffffffffu, partial, lane & ~7);

        const float nm = fmaxf(m, logit);
        const float scale = __expf(m - nm);
        const float p = __expf(logit - nm);
        s = fmaf(s, scale, p);
        m = nm;
        #pragma unroll
        for (int k = 0; k < 8; k++)
            accv[k] = fmaf(accv[k], scale, p * xlv[k]);
    };

    const int jb = g_off[i], je = g_off[i + 1];
    int jj = jb;
    for (; jj + 3 < je; jj += 4) {
        const int s0 = g_csr[jj],     s1 = g_csr[jj + 1];
        const int s2 = g_csr[jj + 2], s3 = g_csr[jj + 3];
        const float4* p0 = (const float4*)(g_xl + (size_t)s0 * HID + cbase);
        const float4* p1 = (const float4*)(g_xl + (size_t)s1 * HID + cbase);
        const float4* p2 = (const float4*)(g_xl + (size_t)s2 * HID + cbase);
        const float4* p3 = (const float4*)(g_xl + (size_t)s3 * HID + cbase);
        float4 a0 = p0[0], b0 = p0[1];
        float4 a1 = p1[0], b1 = p1[1];
        float4 a2 = p2[0], b2 = p2[1];
        float4 a3 = p3[0], b3 = p3[1];
        process(a0, b0);
        process(a1, b1);
        process(a2, b2);
        process(a3, b3);
    }
    for (; jj < je; jj++) {
        const int s0 = g_csr[jj];
        const float4* p0 = (const float4*)(g_xl + (size_t)s0 * HID + cbase);
        float4 a0 = p0[0], b0 = p0[1];
        process(a0, b0);
    }

    const float inv = 1.f / fmaxf(s, 1e-16f);
    float4* ap = (float4*)(g_agg + (size_t)i * HID + cbase);
    ap[0] = make_float4(accv[0] * inv, accv[1] * inv, accv[2] * inv, accv[3] * inv);
    ap[1] = make_float4(accv[4] * inv, accv[5] * inv, accv[6] * inv, accv[7] * inv);
}

// ---------------- skip-add + LayerNorm + relu -> h halves -----------------
__global__ __launch_bounds__(256)
void skipln_kernel(const float* __restrict__ gatb_l,
                   const float* __restrict__ lng_l,
                   const float* __restrict__ lnb_l) {
    const int warp = threadIdx.x >> 5;
    const int lane = threadIdx.x & 31;
    const int i = blockIdx.x * 8 + warp;
    if (i >= NND) return;
    const int cbase = lane * 8;

    float v[8];
    {
        const float4* ap = (const float4*)(g_agg + (size_t)i * HID + cbase);
        const float4* sp = (const float4*)(g_skip + (size_t)i * HID + cbase);
        float4 a0 = ap[0], a1 = ap[1];
        float4 s0 = sp[0], s1 = sp[1];
        float ag[8] = {a0.x, a0.y, a0.z, a0.w, a1.x, a1.y, a1.z, a1.w};
        float sk[8] = {s0.x, s0.y, s0.z, s0.w, s1.x, s1.y, s1.z, s1.w};
        #pragma unroll
        for (int k = 0; k < 8; k++)
            v[k] = ag[k] + gatb_l[cbase + k] + sk[k];
    }

    float lsum = 0.f;
    #pragma unroll
    for (int k = 0; k < 8; k++) lsum += v[k];
    #pragma unroll
    for (int d = 16; d > 0; d >>= 1) lsum += __shfl_xor_sync(0xffffffffu, lsum, d);
    const float mu = lsum * (1.f / HID);

    float vsum = 0.f;
    #pragma unroll
    for (int k = 0; k < 8; k++) { float ddd = v[k] - mu; vsum = fmaf(ddd, ddd, vsum); }
    #pragma unroll
    for (int d = 16; d > 0; d >>= 1) vsum += __shfl_xor_sync(0xffffffffu, vsum, d);
    const float rstd = rsqrtf(vsum * (1.f / HID) + 1e-5f);

    __half hh[8], hl[8];
    #pragma unroll
    for (int k = 0; k < 8; k++) {
        float t = lng_l[cbase + k] * (v[k] - mu) * rstd + lnb_l[cbase + k];
        t = fmaxf(t, 0.f);
        __half hi = __float2half_rn(t);
        hh[k] = hi;
        hl[k] = __float2half_rn(t - __half2float(hi));
    }
    size_t off = (size_t)i * HID + cbase;
    *(uint4*)(g_hh + off) = *(const uint4*)hh;
    *(uint4*)(g_hl + off) = *(const uint4*)hl;
}

// ---------------- head sum: out[i] = sum of 4 partials + b2 ----------------
__global__ __launch_bounds__(256)
void head_sum_kernel(const float* __restrict__ b2, float* __restrict__ out) {
    int i = blockIdx.x * blockDim.x + threadIdx.x;
    if (i < NND) {
        float4 p = *(const float4*)(g_part + i * 4);
        out[i] = p.x + p.y + p.z + p.w + b2[0];
    }
}

// ---------------- launch ----------------
extern "C" void kernel_launch(void* const* d_in, const int* in_sizes, int n_in,
                              void* d_out, int out_size) {
    const float* x      = (const float*)d_in[0];
    const void*  ei     = d_in[1];                 // int32 OR int64 (device-detected)
    const float* enc_W  = (const float*)d_in[4];
    const float* enc_b  = (const float*)d_in[5];
    const float* Wl     = (const float*)d_in[6];
    const float* Wr     = (const float*)d_in[7];
    const float* att    = (const float*)d_in[8];
    const float* gat_b  = (const float*)d_in[9];
    const float* skip_W = (const float*)d_in[10];
    const float* skip_b = (const float*)d_in[11];
    const float* ln_g   = (const float*)d_in[12];
    const float* ln_b   = (const float*)d_in[13];
    const float* out_W1 = (const float*)d_in[14];
    const float* out_b1 = (const float*)d_in[15];
    const float* out_W2 = (const float*)d_in[16];
    const float* out_b2 = (const float*)d_in[17];
    float* out = (float*)d_out;

    const int NBLK_SCAN = (NND + 511) / 512;
    const int NTB = (NND + 127) / 128;            // 196
    const dim3 grid1(NTB, 2);
    const dim3 grid2(NTB, 4);                      // dual (xl, xr)

    cudaStream_t s2;
    cudaStreamCreateWithFlags(&s2, cudaStreamNonBlocking);
    cudaEvent_t evFork, evCsr, evH[NLAYERS], evSkip[NLAYERS];
    cudaEventCreateWithFlags(&evFork, cudaEventDisableTiming);
    cudaEventCreateWithFlags(&evCsr, cudaEventDisableTiming);
    for (int L = 0; L < NLAYERS; L++) {
        cudaEventCreateWithFlags(&evH[L], cudaEventDisableTiming);
        cudaEventCreateWithFlags(&evSkip[L], cudaEventDisableTiming);
    }

    cudaEventRecord(evFork, 0);
    cudaStreamWaitEvent(s2, evFork, 0);

    // side stream: CSR build (atomic/latency-bound)
    zerodetect_kernel<<<(NND + 511) / 512, 512, 0, s2>>>(ei);
    count_kernel<<<(ETOT + 511) / 512, 512, 0, s2>>>(ei);
    scan1_kernel<<<NBLK_SCAN, 512, 0, s2>>>();
    scan2_kernel<<<1, 64, 0, s2>>>(NBLK_SCAN);
    scan3_kernel<<<NBLK_SCAN, 512, 0, s2>>>();
    fill_kernel<<<(ETOT + 511) / 512, 512, 0, s2>>>(ei);
    cudaEventRecord(evCsr, s2);

    // main stream: splits + encoder
    split_all_kernel<<<(WTOT + 255) / 256, 256>>>(enc_W, Wl, Wr, skip_W, out_W1);
    split_x_kernel<<<(NND * INDIM + 255) / 256, 256>>>(x);
    hgemm_kernel<1, 1><<<grid1, 256>>>(1, WOFF_ENC, 0, 0, enc_b, nullptr, nullptr,
                                       0, 0, 0, NND, INDIM);

    for (int L = 0; L < NLAYERS; L++) {
        // h ready -> fork skip GEMM onto s2, overlapping with xl/xr GEMM + gat edge
        cudaEventRecord(evH[L], 0);
        cudaStreamWaitEvent(s2, evH[L], 0);
        hgemm_kernel<1, 0><<<grid1, 256, 0, s2>>>(0, WOFF_SK + L * 65536, 0, 0,
                                                  skip_b + L * HID, nullptr, nullptr,
                                                  3, 3, 3, NND, HID);
        cudaEventRecord(evSkip[L], s2);

        // main: xl = h@Wl, xr = h@Wr (dual)
        hgemm_kernel<2, 0><<<grid2, 256>>>(0, WOFF_WL + L * 65536,
                                           WOFF_WR + L * 65536, 0,
                                           nullptr, nullptr, nullptr,
                                           1, 2, 0, NND, HID);

        if (L == 0) cudaStreamWaitEvent(0, evCsr, 0);   // gat needs CSR

        gat_edge_kernel<<<(NND + 7) / 8, 256>>>(att + L * NHEADS * HEADDIM);

        cudaStreamWaitEvent(0, evSkip[L], 0);           // join skip before epilogue
        skipln_kernel<<<(NND + 7) / 8, 256>>>(gat_b + L * HID,
                                              ln_g + L * HID, ln_b + L * HID);
    }

    // fused output head: partial dots in GEMM epilogue, then tiny sum
    hgemm_kernel<1, 2><<<grid1, 256>>>(0, WOFF_OUT, 0, 0, out_b1, nullptr, out_W2,
                                       1, 1, 1, NND, HID);
    head_sum_kernel<<<(NND + 255) / 256, 256>>>(out_b2, out);

    (void)in_sizes; (void)n_in; (void)out_size;
}

// round 17
// speedup vs baseline: 1.0365x; 1.0365x over previous
#include <cuda_runtime.h>
#include <mma.h>
#include <cuda_fp16.h>
#include <math.h>
#include <stdint.h>

using namespace nvcuda;

// ---------------- problem constants ----------------
#define NND     25000
#define INDIM   128
#define HID     256
#define NHEADS  4
#define HEADDIM 64
#define NLAYERS 3
#define NE      500000
#define ETOT    (NE + NND)   // reference appends self-loops

// packed weight-split layout (element offsets)
#define WOFF_ENC  0
#define WOFF_WL   32768
#define WOFF_WR   229376
#define WOFF_SK   425984
#define WOFF_OUT  622592
#define WTOT      688128

// ---------------- device scratch (static, no allocation) ----------------
__device__ float  g_xl  [NND * HID];
__device__ float  g_xr  [NND * HID];
__device__ float  g_skip[NND * HID];
__device__ float  g_part[NND * 4];     // head partial dots
__device__ __half g_hh  [NND * HID];   // h hi-halves
__device__ __half g_hl  [NND * HID];   // h lo-halves
__device__ __half g_exh [NND * INDIM]; // x hi
__device__ __half g_exl [NND * INDIM]; // x lo
__device__ __half g_wh  [WTOT];        // weights hi
__device__ __half g_wl  [WTOT];        // weights lo
__device__ int    g_deg [NND];
__device__ int    g_off [NND + 1];
__device__ int    g_cur [NND];
__device__ int    g_csr [ETOT];
__device__ int    g_incl[NND];
__device__ int    g_bsum[64];
__device__ int    g_is64;

// float scratch ids: 1=xl 2=xr 3=skip
__device__ __forceinline__ float* fbuf_ptr(int id) {
    switch (id) {
        case 1: return g_xl;
        case 2: return g_xr;
        default: return g_skip;
    }
}

__device__ __forceinline__ int load_idx(const void* ei, long long pos) {
    if (g_is64) return (int)((const long long*)ei)[pos];
    return ((const int*)ei)[pos];
}

// ---------------- hi/lo split helpers ----------------
__global__ void split_all_kernel(const float* __restrict__ encW,
                                 const float* __restrict__ Wl,
                                 const float* __restrict__ Wr,
                                 const float* __restrict__ skW,
                                 const float* __restrict__ outW) {
    int i = blockIdx.x * blockDim.x + threadIdx.x;
    if (i >= WTOT) return;
    const float* src; int local;
    if (i < WOFF_WL)       { src = encW; local = i - WOFF_ENC; }
    else if (i < WOFF_SK)  { src = (i < WOFF_WR) ? Wl : Wr;
                             local = i - ((i < WOFF_WR) ? WOFF_WL : WOFF_WR); }
    else if (i < WOFF_OUT) { src = skW;  local = i - WOFF_SK; }
    else                   { src = outW; local = i - WOFF_OUT; }
    float v = src[local];
    __half hi = __float2half_rn(v);
    g_wh[i] = hi;
    g_wl[i] = __float2half_rn(v - __half2float(hi));
}

__global__ void split_x_kernel(const float* __restrict__ src) {
    int i = blockIdx.x * blockDim.x + threadIdx.x;
    if (i < NND * INDIM) {
        float v = src[i];
        __half hi = __float2half_rn(v);
        g_exh[i] = hi;
        g_exl[i] = __float2half_rn(v - __half2float(hi));
    }
}

// ---------------- CSR construction ----------------
// zero degrees + dtype-detect (edge_index declared int64, but JAX x64-disabled
// silently yields int32; true int64 <2^31 has all odd 32-bit words zero)
__global__ void zerodetect_kernel(const void* ei) {
    int i = blockIdx.x * blockDim.x + threadIdx.x;
    if (i < NND) g_deg[i] = 0;
    if (blockIdx.x == 0 && threadIdx.x == 0) {
        const int* w = (const int*)ei;
        int nz = 0;
        #pragma unroll
        for (int k = 0; k < 64; k++) nz |= w[2 * k + 1];
        g_is64 = (nz == 0) ? 1 : 0;
    }
}

// 2 edges per thread
__global__ void count_kernel(const void* __restrict__ ei) {
    int e0 = (blockIdx.x * blockDim.x + threadIdx.x) * 2;
    #pragma unroll
    for (int q = 0; q < 2; q++) {
        int e = e0 + q;
        if (e < ETOT) {
            int dst = (e < NE) ? load_idx(ei, (long long)NE + e) : (e - NE);
            atomicAdd(&g_deg[dst], 1);
        }
    }
}

__global__ void scan1_kernel() {
    __shared__ int sh[512];
    int idx = blockIdx.x * 512 + threadIdx.x;
    int v = (idx < NND) ? g_deg[idx] : 0;
    sh[threadIdx.x] = v;
    __syncthreads();
    #pragma unroll
    for (int d = 1; d < 512; d <<= 1) {
        int t = (threadIdx.x >= d) ? sh[threadIdx.x - d] : 0;
        __syncthreads();
        sh[threadIdx.x] += t;
        __syncthreads();
    }
    if (idx < NND) g_incl[idx] = sh[threadIdx.x];
    if (threadIdx.x == 511) g_bsum[blockIdx.x] = sh[511];
}

__global__ void scan2_kernel(int nblk) {
    __shared__ int sh[64];
    int t = threadIdx.x;
    int v = (t < nblk) ? g_bsum[t] : 0;
    sh[t] = v;
    __syncthreads();
    #pragma unroll
    for (int d = 1; d < 64; d <<= 1) {
        int u = (t >= d) ? sh[t - d] : 0;
        __syncthreads();
        sh[t] += u;
        __syncthreads();
    }
    if (t < nblk) g_bsum[t] = sh[t] - v;     // exclusive
    if (t == nblk - 1) g_off[NND] = sh[t];   // total
}

__global__ void scan3_kernel() {
    int idx = blockIdx.x * 512 + threadIdx.x;
    if (idx < NND) {
        int e = g_incl[idx] - g_deg[idx] + g_bsum[blockIdx.x];
        g_off[idx] = e;
        g_cur[idx] = e;
    }
}

// 2 edges per thread
__global__ void fill_kernel(const void* __restrict__ ei) {
    int e0 = (blockIdx.x * blockDim.x + threadIdx.x) * 2;
    #pragma unroll
    for (int q = 0; q < 2; q++) {
        int e = e0 + q;
        if (e < ETOT) {
            int src, dst;
            if (e < NE) { src = load_idx(ei, e); dst = load_idx(ei, (long long)NE + e); }
            else        { src = e - NE;          dst = e - NE; }
            int pos = atomicAdd(&g_cur[dst], 1);
            g_csr[pos] = src;
        }
    }
}

// ---------------- cp.async helpers ----------------
__device__ __forceinline__ void cp_async16(unsigned saddr, const void* gptr, bool pred) {
    int sz = pred ? 16 : 0;
    asm volatile("cp.async.cg.shared.global [%0], [%1], 16, %2;\n"
                 :: "r"(saddr), "l"(gptr), "r"(sz));
}
#define CP_COMMIT() asm volatile("cp.async.commit_group;\n" ::: "memory")
#define CP_WAIT0()  asm volatile("cp.async.wait_group 0;\n" ::: "memory")

// ---------------- 3xFP16-split tensor-core GEMM, cp.async double-buffered --
// C[N,256] = A[N,K] @ B[K,256], operands pre-split hi/lo.
// D = Ahi*Bhi + Ahi*Blo + Alo*Bhi, fp32 acc. Block 128x128, 8 warps,
// warp tile 32x64 = 2x4 wmma m16n16k16, BK=16.
// MODE: 0 = fp32 C (+bias,relu when bias nonnull)
//       1 = write h hi/lo halves (encoder)
//       2 = fused head: bias+relu then dot with W2 -> g_part
// blockIdx.y: j = y>>1 selects B/C/bias, bc = y&1 selects 128-col half.

#define A_LDM 24    // halves; 48B row stride
#define B_LDM 136   // halves; 272B row stride
#define ASTAGE_B 12288
#define BSTAGE_B 8704
#define SMEM_TILES (2*ASTAGE_B + 2*BSTAGE_B)   // 41984

template <int NB, int MODE>
__global__ __launch_bounds__(256, 2)
void hgemm_kernel(int aId,                       // 0: g_hh/g_hl (K=256), 1: g_exh/g_exl (K=128)
                  int bOff0, int bOff1, int bOff2,
                  const float* __restrict__ bias0, const float* __restrict__ bias2,
                  const float* __restrict__ w2,
                  int c0, int c1, int c2,
                  int Nrows, int K) {
    const __half* Ah = aId ? g_exh : g_hh;
    const __half* Al = aId ? g_exl : g_hl;

    const int j  = blockIdx.y >> 1;
    const int bc = blockIdx.y & 1;
    const int bOff = (NB == 1 || j == 0) ? bOff0 : ((j == 1) ? bOff1 : bOff2);
    float* C = fbuf_ptr((NB == 1 || j == 0) ? c0 : ((j == 1) ? c1 : c2));
    const float* bias = (NB == 1 || j == 0) ? bias0 : ((j == 2) ? bias2 : nullptr);

    __shared__ __align__(16) unsigned char smem_raw[SMEM_TILES];
    const unsigned sbase = (unsigned)__cvta_generic_to_shared(smem_raw);

    const int tid  = threadIdx.x;
    const int lane = tid & 31;
    const int wid  = tid >> 5;
    const int warp_m = wid & 3;
    const int warp_n = wid >> 2;

    const int br = blockIdx.x;
    const int rowBase = br * 128 + warp_m * 32;
    const int colBase = bc * 128 + warp_n * 64;

    wmma::fragment<wmma::accumulator, 16, 16, 16, float> acc[2][4];
    #pragma unroll
    for (int mt = 0; mt < 2; mt++)
        #pragma unroll
        for (int nt = 0; nt < 4; nt++)
            wmma::fill_fragment(acc[mt][nt], 0.f);

    const int arow = tid >> 1, acol = (tid & 1) * 8;
    const int bk = tid >> 4, bn = (tid & 15) * 8;

    const int rg = br * 128 + arow;
    const bool aOK = (rg < Nrows);
    const int rgs = aOK ? rg : 0;
    const int nIter = K >> 4;

    const unsigned aslot = (unsigned)(arow * A_LDM + acol) * 2u;
    const unsigned bslot = (unsigned)(bk * B_LDM + bn) * 2u;

    auto issueTile = [&](int kt, int s) {
        int k0 = kt << 4;
        size_t aoff = (size_t)rgs * K + k0 + acol;
        cp_async16(sbase + s * ASTAGE_B + aslot, Ah + aoff, aOK);
        cp_async16(sbase + s * ASTAGE_B + ASTAGE_B / 2 + aslot, Al + aoff, aOK);
        size_t boff = (size_t)bOff + (size_t)(k0 + bk) * HID + bc * 128 + bn;
        cp_async16(sbase + 2 * ASTAGE_B + s * BSTAGE_B + bslot, g_wh + boff, true);
        cp_async16(sbase + 2 * ASTAGE_B + s * BSTAGE_B + BSTAGE_B / 2 + bslot, g_wl + boff, true);
    };
    auto AhS = [&](int s) { return (__half*)(smem_raw + s * ASTAGE_B); };
    auto AlS = [&](int s) { return (__half*)(smem_raw + s * ASTAGE_B + ASTAGE_B / 2); };
    auto BhS = [&](int s) { return (__half*)(smem_raw + 2 * ASTAGE_B + s * BSTAGE_B); };
    auto BlS = [&](int s) { return (__half*)(smem_raw + 2 * ASTAGE_B + s * BSTAGE_B + BSTAGE_B / 2); };

    issueTile(0, 0);
    CP_COMMIT();

    for (int kt = 0; kt < nIter; kt++) {
        const int cur = kt & 1, nxt = cur ^ 1;
        CP_WAIT0();
        __syncthreads();
        if (kt + 1 < nIter) {
            issueTile(kt + 1, nxt);
            CP_COMMIT();
        }

        wmma::fragment<wmma::matrix_a, 16, 16, 16, __half, wmma::row_major> a_hi[2], a_lo[2];
        #pragma unroll
        for (int mt = 0; mt < 2; mt++) {
            int mr = warp_m * 32 + mt * 16;
            wmma::load_matrix_sync(a_hi[mt], AhS(cur) + mr * A_LDM, A_LDM);
            wmma::load_matrix_sync(a_lo[mt], AlS(cur) + mr * A_LDM, A_LDM);
        }
        #pragma unroll
        for (int nt = 0; nt < 4; nt++) {
            int nc = warp_n * 64 + nt * 16;
            wmma::fragment<wmma::matrix_b, 16, 16, 16, __half, wmma::row_major> b_hi, b_lo;
            wmma::load_matrix_sync(b_hi, BhS(cur) + nc, B_LDM);
            wmma::load_matrix_sync(b_lo, BlS(cur) + nc, B_LDM);
            #pragma unroll
            for (int mt = 0; mt < 2; mt++) {
                wmma::mma_sync(acc[mt][nt], a_hi[mt], b_hi, acc[mt][nt]);
                wmma::mma_sync(acc[mt][nt], a_hi[mt], b_lo, acc[mt][nt]);
                wmma::mma_sync(acc[mt][nt], a_lo[mt], b_hi, acc[mt][nt]);
            }
        }
    }
    __syncthreads();

    // ---- epilogue: sbuf aliases tile memory
    float* sbuf = (float*)smem_raw + wid * 16 * 20;
    #pragma unroll
    for (int mt = 0; mt < 2; mt++) {
        float pdot = 0.f;
        const int r  = lane >> 1;
        const int cb = (lane & 1) * 8;
        const int grow = rowBase + mt * 16 + r;
        #pragma unroll
        for (int nt = 0; nt < 4; nt++) {
            wmma::store_matrix_sync(sbuf, acc[mt][nt], 20, wmma::mem_row_major);
            __syncwarp();
            int gcol = colBase + nt * 16 + cb;
            if (grow < Nrows) {
                float vv[8];
                #pragma unroll
                for (int i = 0; i < 8; i++) {
                    float t = sbuf[r * 20 + cb + i];
                    if (bias) t = fmaxf(t + bias[gcol + i], 0.f);
                    vv[i] = t;
                }
                if (MODE == 2) {
                    #pragma unroll
                    for (int i = 0; i < 8; i++)
                        pdot = fmaf(vv[i], w2[gcol + i], pdot);
                } else if (MODE == 1) {
                    __half hh[8], hl[8];
                    #pragma unroll
                    for (int i = 0; i < 8; i++) {
                        __half hi = __float2half_rn(vv[i]);
                        hh[i] = hi;
                        hl[i] = __float2half_rn(vv[i] - __half2float(hi));
                    }
                    size_t off = (size_t)grow * HID + gcol;
                    *(uint4*)(g_hh + off) = *(const uint4*)hh;
                    *(uint4*)(g_hl + off) = *(const uint4*)hl;
                } else {
                    float4* cp = (float4*)(C + (size_t)grow * HID + gcol);
                    cp[0] = make_float4(vv[0], vv[1], vv[2], vv[3]);
                    cp[1] = make_float4(vv[4], vv[5], vv[6], vv[7]);
                }
            }
            __syncwarp();
        }
        if (MODE == 2) {
            pdot += __shfl_xor_sync(0xffffffffu, pdot, 1);
            if ((lane & 1) == 0 && grow < Nrows)
                g_part[grow * 4 + bc * 2 + warp_n] = pdot;
        }
    }
}

// ---------------- fused GATv2 edge aggregation + bias + skip + LN + relu ----------------
// one warp per node; lane owns channels [lane*8, lane*8+8), head = lane/8
// edge loop unrolled x4 with next-group CSR-index prefetch.
__global__ __launch_bounds__(256)
void gat_edge_ln_kernel(const float* __restrict__ att_l,
                        const float* __restrict__ gatb_l,
                        const float* __restrict__ lng_l,
                        const float* __restrict__ lnb_l) {
    const int warp = threadIdx.x >> 5;
    const int lane = threadIdx.x & 31;
    const int i = blockIdx.x * 8 + warp;
    if (i >= NND) return;

    const int head = lane >> 3;
    const int cbase = lane * 8;

    float xr[8], attv[8];
    {
        const float4* p = (const float4*)(g_xr + (size_t)i * HID + cbase);
        float4 a = p[0], b = p[1];
        xr[0]=a.x; xr[1]=a.y; xr[2]=a.z; xr[3]=a.w;
        xr[4]=b.x; xr[5]=b.y; xr[6]=b.z; xr[7]=b.w;
        #pragma unroll
        for (int k = 0; k < 8; k++)
            attv[k] = att_l[head * HEADDIM + (lane & 7) * 8 + k];
    }

    float m = -INFINITY, s = 0.f;
    float accv[8];
    #pragma unroll
    for (int k = 0; k < 8; k++) accv[k] = 0.f;

    auto process = [&](const float4& a, const float4& b) {
        float xlv[8] = {a.x, a.y, a.z, a.w, b.x, b.y, b.z, b.w};
        float partial = 0.f;
        #pragma unroll
        for (int k = 0; k < 8; k++) {
            float t = xlv[k] + xr[k];
            t = (t > 0.f) ? t : 0.2f * t;          // leaky_relu 0.2
            partial = fmaf(t, attv[k], partial);
        }
        partial += __shfl_down_sync(0xffffffffu, partial, 4);
        partial += __shfl_down_sync(0xffffffffu, partial, 2);
        partial += __shfl_down_sync(0xffffffffu, partial, 1);
        const float logit = __shfl_sync(0xffffffffu, partial, lane & ~7);

        const float nm = fmaxf(m, logit);
        const float scale = __expf(m - nm);
        const float p = __expf(logit - nm);
        s = fmaf(s, scale, p);
        m = nm;
        #pragma unroll
        for (int k = 0; k < 8; k++)
            accv[k] = fmaf(accv[k], scale, p * xlv[k]);
    };

    const int jb = g_off[i], je = g_off[i + 1];
    int jj = jb;
    int nidx0 = 0, nidx1 = 0, nidx2 = 0, nidx3 = 0;
    if (jj + 3 < je) {
        nidx0 = g_csr[jj];     nidx1 = g_csr[jj + 1];
        nidx2 = g_csr[jj + 2]; nidx3 = g_csr[jj + 3];
    }
    while (jj + 3 < je) {
        const int s0 = nidx0, s1 = nidx1, s2 = nidx2, s3 = nidx3;
        jj += 4;
        const float4* p0 = (const float4*)(g_xl + (size_t)s0 * HID + cbase);
        const float4* p1 = (const float4*)(g_xl + (size_t)s1 * HID + cbase);
        const float4* p2 = (const float4*)(g_xl + (size_t)s2 * HID + cbase);
        const float4* p3 = (const float4*)(g_xl + (size_t)s3 * HID + cbase);
        float4 a0 = p0[0], b0 = p0[1];
        float4 a1 = p1[0], b1 = p1[1];
        float4 a2 = p2[0], b2 = p2[1];
        float4 a3 = p3[0], b3 = p3[1];
        if (jj + 3 < je) {       // prefetch next group's indices
            nidx0 = g_csr[jj];     nidx1 = g_csr[jj + 1];
            nidx2 = g_csr[jj + 2]; nidx3 = g_csr[jj + 3];
        }
        process(a0, b0);
        process(a1, b1);
        process(a2, b2);
        process(a3, b3);
    }
    for (; jj < je; jj++) {
        const int s0 = g_csr[jj];
        const float4* p0 = (const float4*)(g_xl + (size_t)s0 * HID + cbase);
        float4 a0 = p0[0], b0 = p0[1];
        process(a0, b0);
    }

    const float inv = 1.f / fmaxf(s, 1e-16f);

    float v[8];
    {
        const float4* sp = (const float4*)(g_skip + (size_t)i * HID + cbase);
        float4 a = sp[0], b = sp[1];
        float sk[8] = {a.x, a.y, a.z, a.w, b.x, b.y, b.z, b.w};
        #pragma unroll
        for (int k = 0; k < 8; k++)
            v[k] = accv[k] * inv + gatb_l[cbase + k] + sk[k];
    }

    float lsum = 0.f;
    #pragma unroll
    for (int k = 0; k < 8; k++) lsum += v[k];
    #pragma unroll
    for (int d = 16; d > 0; d >>= 1) lsum += __shfl_xor_sync(0xffffffffu, lsum, d);
    const float mu = lsum * (1.f / HID);

    float vsum = 0.f;
    #pragma unroll
    for (int k = 0; k < 8; k++) { float ddd = v[k] - mu; vsum = fmaf(ddd, ddd, vsum); }
    #pragma unroll
    for (int d = 16; d > 0; d >>= 1) vsum += __shfl_xor_sync(0xffffffffu, vsum, d);
    const float rstd = rsqrtf(vsum * (1.f / HID) + 1e-5f);

    __half hh[8], hl[8];
    #pragma unroll
    for (int k = 0; k < 8; k++) {
        float t = lng_l[cbase + k] * (v[k] - mu) * rstd + lnb_l[cbase + k];
        t = fmaxf(t, 0.f);
        __half hi = __float2half_rn(t);
        hh[k] = hi;
        hl[k] = __float2half_rn(t - __half2float(hi));
    }
    size_t off = (size_t)i * HID + cbase;
    *(uint4*)(g_hh + off) = *(const uint4*)hh;
    *(uint4*)(g_hl + off) = *(const uint4*)hl;
}

// ---------------- head sum: out[i] = sum of 4 partials + b2 ----------------
__global__ __launch_bounds__(256)
void head_sum_kernel(const float* __restrict__ b2, float* __restrict__ out) {
    int i = blockIdx.x * blockDim.x + threadIdx.x;
    if (i < NND) {
        float4 p = *(const float4*)(g_part + i * 4);
        out[i] = p.x + p.y + p.z + p.w + b2[0];
    }
}

// ---------------- launch ----------------
extern "C" void kernel_launch(void* const* d_in, const int* in_sizes, int n_in,
                              void* d_out, int out_size) {
    const float* x      = (const float*)d_in[0];
    const void*  ei     = d_in[1];                 // int32 OR int64 (device-detected)
    const float* enc_W  = (const float*)d_in[4];
    const float* enc_b  = (const float*)d_in[5];
    const float* Wl     = (const float*)d_in[6];
    const float* Wr     = (const float*)d_in[7];
    const float* att    = (const float*)d_in[8];
    const float* gat_b  = (const float*)d_in[9];
    const float* skip_W = (const float*)d_in[10];
    const float* skip_b = (const float*)d_in[11];
    const float* ln_g   = (const float*)d_in[12];
    const float* ln_b   = (const float*)d_in[13];
    const float* out_W1 = (const float*)d_in[14];
    const float* out_b1 = (const float*)d_in[15];
    const float* out_W2 = (const float*)d_in[16];
    const float* out_b2 = (const float*)d_in[17];
    float* out = (float*)d_out;

    const int NBLK_SCAN = (NND + 511) / 512;
    const int NTB = (NND + 127) / 128;            // 196
    const dim3 grid1(NTB, 2);
    const dim3 grid3(NTB, 6);

    cudaStream_t s2;
    cudaStreamCreateWithFlags(&s2, cudaStreamNonBlocking);
    cudaEvent_t evFork, evCsr;
    cudaEventCreateWithFlags(&evFork, cudaEventDisableTiming);
    cudaEventCreateWithFlags(&evCsr, cudaEventDisableTiming);

    cudaEventRecord(evFork, 0);
    cudaStreamWaitEvent(s2, evFork, 0);

    // side stream: CSR build (atomic/latency-bound, low SM occupancy)
    zerodetect_kernel<<<(NND + 511) / 512, 512, 0, s2>>>(ei);
    count_kernel<<<(ETOT / 2 + 512) / 512, 512, 0, s2>>>(ei);
    scan1_kernel<<<NBLK_SCAN, 512, 0, s2>>>();
    scan2_kernel<<<1, 64, 0, s2>>>(NBLK_SCAN);
    scan3_kernel<<<NBLK_SCAN, 512, 0, s2>>>();
    fill_kernel<<<(ETOT / 2 + 512) / 512, 512, 0, s2>>>(ei);
    cudaEventRecord(evCsr, s2);

    // main stream: splits + encoder + first triple GEMM (tensor/BW-bound)
    split_all_kernel<<<(WTOT + 255) / 256, 256>>>(enc_W, Wl, Wr, skip_W, out_W1);
    split_x_kernel<<<(NND * INDIM + 255) / 256, 256>>>(x);

    // encoder: h = relu(x @ enc_W + enc_b) -> halves
    hgemm_kernel<1, 1><<<grid1, 256>>>(1, WOFF_ENC, 0, 0, enc_b, nullptr, nullptr,
                                       0, 0, 0, NND, INDIM);

    for (int L = 0; L < NLAYERS; L++) {
        // xl = h@Wl, xr = h@Wr, skip = relu(h@skW + skip_b) — one launch
        hgemm_kernel<3, 0><<<grid3, 256>>>(0, WOFF_WL + L * 65536,
                                           WOFF_WR + L * 65536,
                                           WOFF_SK + L * 65536,
                                           nullptr, skip_b + L * HID, nullptr,
                                           1, 2, 3, NND, HID);

        if (L == 0) cudaStreamWaitEvent(0, evCsr, 0);   // join: gat needs CSR

        gat_edge_ln_kernel<<<(NND + 7) / 8, 256>>>(
            att + L * NHEADS * HEADDIM, gat_b + L * HID,
            ln_g + L * HID, ln_b + L * HID);
    }

    // fused output head: partial dots in GEMM epilogue, then tiny sum
    hgemm_kernel<1, 2><<<grid1, 256>>>(0, WOFF_OUT, 0, 0, out_b1, nullptr, out_W2,
                                       1, 1, 1, NND, HID);
    head_sum_kernel<<<(NND + 255) / 256, 256>>>(out_b2, out);

    (void)in_sizes; (void)n_in; (void)out_size;
}